// round 1
// baseline (speedup 1.0000x reference)
#include <cuda_runtime.h>

#define NF 40
#define NP 780      // 40*39/2 pairs
#define ED 64
#define AS 32
#define THREADS 256
#define XPITCH 65   // padded row pitch for xs to avoid bank conflicts

__global__ __launch_bounds__(THREADS) void afm_kernel(
    const float* __restrict__ x,
    const float* __restrict__ attn_w,
    const float* __restrict__ attn_b,
    const float* __restrict__ proj_w,
    const float* __restrict__ proj_b,
    const float* __restrict__ fc_w,
    const float* __restrict__ fc_b,
    float* __restrict__ out)
{
    __shared__ float xs[NF * XPITCH];                 // 10400 B
    __shared__ __align__(16) float Ws[ED * AS];       // 8192 B, row-major [d][a]
    __shared__ float logits_s[NP];                    // 3120 B
    __shared__ unsigned char pi_s[NP], pj_s[NP];      // 1560 B
    __shared__ float pw_s[AS], ab_s[AS], fw_s[ED];
    __shared__ float rmax[8], rsum[8];
    __shared__ float part[8 * 64];                    // per-warp partial attn_out
    __shared__ float red_s[64];

    const int tid  = threadIdx.x;
    const int lane = tid & 31;
    const int wid  = tid >> 5;
    const int b    = blockIdx.x;

    // ---- Phase 1: stage inputs into smem ----
    const float* xb = x + (long long)b * (NF * ED);
    for (int idx = tid; idx < NF * ED; idx += THREADS)
        xs[(idx >> 6) * XPITCH + (idx & 63)] = xb[idx];
    for (int idx = tid; idx < ED * AS; idx += THREADS)
        Ws[idx] = attn_w[idx];
    if (tid < AS) { pw_s[tid] = proj_w[tid]; ab_s[tid] = attn_b[tid]; }
    if (tid < ED) fw_s[tid] = fc_w[tid];

    // pair -> (i, j) table (upper triangle, row-major order, matches np.triu_indices)
    for (int p = tid; p < NP; p += THREADS) {
        int i = 0, rem = p;
        while (rem >= NF - 1 - i) { rem -= NF - 1 - i; ++i; }
        pi_s[p] = (unsigned char)i;
        pj_s[p] = (unsigned char)(i + 1 + rem);
    }
    const float pb = proj_b[0];
    __syncthreads();

    // ---- Phase 2: per-pair GEMM (h = relu(ip @ W + b)), proj -> logit ----
    for (int p = tid; p < NP; p += THREADS) {
        const int ib = pi_s[p] * XPITCH;
        const int jb = pj_s[p] * XPITCH;

        unsigned long long h[16];
#pragma unroll
        for (int k = 0; k < 16; ++k) {
            asm("mov.b64 %0, {%1, %2};"
                : "=l"(h[k]) : "f"(ab_s[2 * k]), "f"(ab_s[2 * k + 1]));
        }

#pragma unroll 8
        for (int d = 0; d < ED; ++d) {
            float ipd = xs[ib + d] * xs[jb + d];
            unsigned long long ip2;
            asm("mov.b64 %0, {%1, %1};" : "=l"(ip2) : "f"(ipd));
            const ulonglong2* Wv = reinterpret_cast<const ulonglong2*>(Ws + d * AS);
#pragma unroll
            for (int k = 0; k < 16; k += 2) {
                ulonglong2 w = Wv[k >> 1];   // LDS.128, warp-uniform address -> broadcast
                asm("fma.rn.f32x2 %0, %1, %2, %0;" : "+l"(h[k])     : "l"(ip2), "l"(w.x));
                asm("fma.rn.f32x2 %0, %1, %2, %0;" : "+l"(h[k + 1]) : "l"(ip2), "l"(w.y));
            }
        }

        float logit = pb;
#pragma unroll
        for (int k = 0; k < 16; ++k) {
            float a0, a1;
            asm("mov.b64 {%0, %1}, %2;" : "=f"(a0), "=f"(a1) : "l"(h[k]));
            logit += fmaxf(a0, 0.f) * pw_s[2 * k] + fmaxf(a1, 0.f) * pw_s[2 * k + 1];
        }
        logits_s[p] = logit;
    }
    __syncthreads();

    // ---- Phase 3: softmax over the 780 pairs (unnormalized; fold 1/S at the end) ----
    float lm = -3.4e38f;
    for (int p = tid; p < NP; p += THREADS) lm = fmaxf(lm, logits_s[p]);
#pragma unroll
    for (int o = 16; o > 0; o >>= 1) lm = fmaxf(lm, __shfl_xor_sync(0xffffffffu, lm, o));
    if (lane == 0) rmax[wid] = lm;
    __syncthreads();

    float gmax = rmax[0];
#pragma unroll
    for (int w = 1; w < 8; ++w) gmax = fmaxf(gmax, rmax[w]);

    float ls = 0.f;
    for (int p = tid; p < NP; p += THREADS) {
        float e = __expf(logits_s[p] - gmax);
        logits_s[p] = e;
        ls += e;
    }
#pragma unroll
    for (int o = 16; o > 0; o >>= 1) ls += __shfl_xor_sync(0xffffffffu, ls, o);
    if (lane == 0) rsum[wid] = ls;
    __syncthreads();

    // ---- Phase 4: weighted sum over pairs (recompute ip), then fc dot ----
    // warp w handles pairs p = w, w+8, ...; lane l handles dims l and l+32
    float accL = 0.f, accH = 0.f;
    for (int p = wid; p < NP; p += 8) {
        float s = logits_s[p];                  // broadcast
        int ib = pi_s[p] * XPITCH;
        int jb = pj_s[p] * XPITCH;
        accL += s * (xs[ib + lane]      * xs[jb + lane]);
        accH += s * (xs[ib + 32 + lane] * xs[jb + 32 + lane]);
    }
    part[wid * 64 + lane]      = accL;
    part[wid * 64 + 32 + lane] = accH;
    __syncthreads();

    if (tid < 64) {
        float v = 0.f;
#pragma unroll
        for (int w = 0; w < 8; ++w) v += part[w * 64 + tid];
        red_s[tid] = v * fw_s[tid];
    }
    __syncthreads();

    if (tid == 0) {
        float S = 0.f;
#pragma unroll
        for (int w = 0; w < 8; ++w) S += rsum[w];
        float t = 0.f;
#pragma unroll
        for (int k = 0; k < 64; ++k) t += red_s[k];
        out[b] = t / S + fc_b[0];
    }
}

extern "C" void kernel_launch(void* const* d_in, const int* in_sizes, int n_in,
                              void* d_out, int out_size)
{
    const float* x      = (const float*)d_in[0];
    const float* attn_w = (const float*)d_in[1];
    const float* attn_b = (const float*)d_in[2];
    const float* proj_w = (const float*)d_in[3];
    const float* proj_b = (const float*)d_in[4];
    const float* fc_w   = (const float*)d_in[5];
    const float* fc_b   = (const float*)d_in[6];
    float* out = (float*)d_out;

    afm_kernel<<<2048, THREADS>>>(x, attn_w, attn_b, proj_w, proj_b, fc_w, fc_b, out);
}